// round 15
// baseline (speedup 1.0000x reference)
#include <cuda_runtime.h>
#include <cuda_bf16.h>
#include <cstdint>

// ---------------- problem constants ----------------
#define B_  8
#define C_  64
#define O_  64
#define H_  128
#define W_  128
#define HW_ (H_*W_)          // 16384
#define NCH_ 8               // channel chunks
#define CPC_ 8               // channels per chunk
#define KB_  80              // padded split-block width (72 data + 8 pad)
#define AST2_ 168            // A row stride (bf16 elems): 160 data + 8 pad
#define BROWS_ 240           // B rows per chunk: [wh 80 | wl 80 | wh 80]
#define BST_ 72              // B row stride (bf16 elems)

#define A_BYTES (128*AST2_*2)            // 43008
#define B_OFF   A_BYTES
#define B_BYTES (BROWS_*BST_*2)          // 34560
#define SMEM_C  (A_BYTES + B_BYTES)      // 77568

// ---------------- scratch (device globals; no allocation allowed) ----------
__device__ __align__(16) float g_xt[B_*HW_*C_];          // NHWC transpose of x
__device__ __align__(16) float4 g_recw[B_*HW_*9];        // folded bilinear weights
__device__ __align__(16) int4   g_recr[B_*HW_*9];        // clamped NHWC offsets
__device__ __align__(16) unsigned short g_wb[NCH_*BROWS_*O_];  // B chunks bf16

// ---------------- helpers ----------------
__device__ __forceinline__ void fma2(unsigned long long &d, unsigned long long a, unsigned long long b) {
    asm("fma.rn.f32x2 %0, %1, %2, %0;" : "+l"(d) : "l"(a), "l"(b));
}
__device__ __forceinline__ unsigned long long pack2(float x, float y) {
    unsigned long long r;
    asm("mov.b64 %0, {%1, %2};" : "=l"(r) : "f"(x), "f"(y));
    return r;
}
__device__ __forceinline__ float2 unpack2(unsigned long long v) {
    float2 r;
    asm("mov.b64 {%0, %1}, %2;" : "=f"(r.x), "=f"(r.y) : "l"(v));
    return r;
}
__device__ __forceinline__ uint32_t smem_u32(const void* p) {
    uint32_t a;
    asm("{ .reg .u64 t; cvta.to.shared.u64 t, %1; cvt.u32.u64 %0, t; }" : "=r"(a) : "l"(p));
    return a;
}
__device__ __forceinline__ void ldsm_x4(uint32_t &r0, uint32_t &r1, uint32_t &r2, uint32_t &r3, uint32_t a) {
    asm volatile("ldmatrix.sync.aligned.m8n8.x4.shared.b16 {%0,%1,%2,%3}, [%4];"
                 : "=r"(r0), "=r"(r1), "=r"(r2), "=r"(r3) : "r"(a));
}
__device__ __forceinline__ void ldsm_x4_t(uint32_t &r0, uint32_t &r1, uint32_t &r2, uint32_t &r3, uint32_t a) {
    asm volatile("ldmatrix.sync.aligned.m8n8.x4.trans.shared.b16 {%0,%1,%2,%3}, [%4];"
                 : "=r"(r0), "=r"(r1), "=r"(r2), "=r"(r3) : "r"(a));
}
__device__ __forceinline__ void mma16816(float* c, uint32_t a0, uint32_t a1, uint32_t a2, uint32_t a3,
                                         uint32_t b0, uint32_t b1) {
    asm volatile(
        "mma.sync.aligned.m16n8k16.row.col.f32.bf16.bf16.f32 "
        "{%0,%1,%2,%3}, {%4,%5,%6,%7}, {%8,%9}, {%0,%1,%2,%3};"
        : "+f"(c[0]), "+f"(c[1]), "+f"(c[2]), "+f"(c[3])
        : "r"(a0), "r"(a1), "r"(a2), "r"(a3), "r"(b0), "r"(b1));
}

// ---------------- kernel A: NCHW -> NHWC transpose of x ----------------
__global__ void transpose_kernel(const float* __restrict__ x) {
    __shared__ float tile[32][33];
    int b  = blockIdx.z;
    int s0 = blockIdx.x * 32;
    int c0 = blockIdx.y * 32;
    #pragma unroll
    for (int i = threadIdx.y; i < 32; i += 8)
        tile[i][threadIdx.x] = x[(size_t)(b*C_ + c0 + i) * HW_ + s0 + threadIdx.x];
    __syncthreads();
    #pragma unroll
    for (int i = threadIdx.y; i < 32; i += 8)
        g_xt[(size_t)(b*HW_ + s0 + i) * C_ + c0 + threadIdx.x] = tile[threadIdx.x][i];
}

// ---------------- kernel A2: build B chunks [cc][240][64] bf16 ----------------
// rows: [0,80): wh(jl=r) ; [80,160): wl(jl=r-80) ; [160,240): wh(jl=r-160)
// jl = ci*9 + t (ci channel-in-chunk); zero when jl >= 72.
__global__ void wb_kernel(const float* __restrict__ w) {
    int idx = blockIdx.x * blockDim.x + threadIdx.x;
    if (idx >= NCH_*BROWS_*O_) return;
    int cc = idx / (BROWS_*O_);
    int r  = (idx / O_) % BROWS_;
    int o  = idx & 63;
    int blk = r / KB_;            // 0,1,2
    int jl  = r % KB_;
    unsigned short outv = 0;
    if (jl < 72) {
        int ci = jl / 9, t = jl % 9;
        int c = cc*CPC_ + ci;
        float v = w[((size_t)o*C_ + c)*9 + t];
        __nv_bfloat16 wh = __float2bfloat16(v);
        if (blk == 1) {
            __nv_bfloat16 wl = __float2bfloat16(v - __bfloat162float(wh));
            outv = *(unsigned short*)&wl;
        } else {
            outv = *(unsigned short*)&wh;
        }
    }
    g_wb[idx] = outv;
}

// ---------------- kernel B: offset+mask conv -> sample records --------------
// 128 threads = one w-row; each thread computes 2 h-rows (h0, h0+1).
__global__ void conv_kernel(const float* __restrict__ x,
                            const float* __restrict__ w_off,
                            const float* __restrict__ b_off,
                            const float* __restrict__ w_mod,
                            const float* __restrict__ b_mod) {
    __shared__ float ws[32*9*28];
    const int w  = threadIdx.x;
    const int h0 = blockIdx.x * 2;
    const int b  = blockIdx.y;

    unsigned long long acc[2][14];
    #pragma unroll
    for (int r = 0; r < 2; ++r)
        #pragma unroll
        for (int j = 0; j < 14; ++j) acc[r][j] = 0ull;

    for (int half = 0; half < 2; ++half) {
        __syncthreads();
        for (int idx = threadIdx.x; idx < 32*9*28; idx += 128) {
            int j = idx % 28;
            int t = (idx / 28) % 9;
            int c = idx / (28*9) + half*32;
            float v = 0.f;
            if (j < 18)      v = w_off[((j*C_ + c) * 9) + t];
            else if (j < 27) v = w_mod[(((j-18)*C_ + c) * 9) + t];
            ws[idx] = v;
        }
        __syncthreads();

        const float* xb = x + (size_t)(b*C_ + half*32) * HW_;
        for (int c = 0; c < 32; ++c) {
            const float* xc = xb + (size_t)c * HW_;
            #pragma unroll
            for (int t = 0; t < 9; ++t) {
                int yy0 = h0 + t/3 - 1;
                int xx  = w  + t%3 - 1;
                float xv0 = 0.f, xv1 = 0.f;
                if (xx >= 0 && xx < W_) {
                    if (yy0 >= 0 && yy0 < H_)     xv0 = xc[yy0*W_ + xx];
                    if (yy0+1 >= 0 && yy0+1 < H_) xv1 = xc[(yy0+1)*W_ + xx];
                }
                unsigned long long x0 = pack2(xv0, xv0);
                unsigned long long x1 = pack2(xv1, xv1);
                const unsigned long long* wp =
                    (const unsigned long long*)&ws[(c*9 + t) * 28];
                #pragma unroll
                for (int j = 0; j < 14; ++j) {
                    unsigned long long wv = wp[j];
                    fma2(acc[0][j], x0, wv);
                    fma2(acc[1][j], x1, wv);
                }
            }
        }
    }

    #pragma unroll
    for (int r = 0; r < 2; ++r) {
        int h = h0 + r;
        float ov[28];
        #pragma unroll
        for (int j = 0; j < 14; ++j) {
            float2 f = unpack2(acc[r][j]);
            ov[2*j] = f.x; ov[2*j+1] = f.y;
        }
        size_t gpx = (size_t)(b*HW_ + h*W_ + w);
        #pragma unroll
        for (int k = 0; k < 9; ++k) {
            float dy = ov[2*k]     + b_off[2*k];
            float dx = ov[2*k + 1] + b_off[2*k + 1];
            float z  = ov[18 + k] + b_mod[k];
            float m  = 2.f / (1.f + expf(-z));
            float py = dy + (float)(h - 1 + k/3);
            float px = dx + (float)(w - 1 + k%3);
            float y0f = floorf(py), x0f = floorf(px);
            float wy = py - y0f,    wx = px - x0f;
            int y0 = (int)y0f, x0 = (int)x0f;
            int y1 = y0 + 1,   x1 = x0 + 1;
            float fy0 = (y0 >= 0 && y0 < H_) ? 1.f : 0.f;
            float fy1 = (y1 >= 0 && y1 < H_) ? 1.f : 0.f;
            float fx0 = (x0 >= 0 && x0 < W_) ? 1.f : 0.f;
            float fx1 = (x1 >= 0 && x1 < W_) ? 1.f : 0.f;
            int y0c = min(max(y0, 0), H_-1), y1c = min(max(y1, 0), H_-1);
            int x0c = min(max(x0, 0), W_-1), x1c = min(max(x1, 0), W_-1);
            g_recw[gpx*9 + k] = make_float4((1.f-wy)*(1.f-wx)*m*fy0*fx0,
                                            (1.f-wy)*wx      *m*fy0*fx1,
                                            wy*(1.f-wx)      *m*fy1*fx0,
                                            wy*wx            *m*fy1*fx1);
            g_recr[gpx*9 + k] = make_int4((y0c*W_ + x0c)*C_, (y0c*W_ + x1c)*C_,
                                          (y1c*W_ + x0c)*C_, (y1c*W_ + x1c)*C_);
        }
    }
}

// ---------------- kernel C: fused sampling + mma.sync (split-dedup A) -------
// CTA = (b,h): 128 px. 8 chunks of 8 channels. A = [vh(80)|vl(80)] per chunk;
// mma does 15 k-steps: 5 vh*wh, 5 vh*wl (A re-pointed at vh), 5 vl*wh.
__global__ void __launch_bounds__(256, 2)
sample_mma_kernel(const float* __restrict__ bias, float* __restrict__ out) {
    extern __shared__ __align__(16) char sm[];
    __nv_bfloat16* Ap = (__nv_bfloat16*)sm;
    float* stg = (float*)sm;                   // epilogue stage (reuses A region)

    const uint32_t sbase = smem_u32(sm);
    const uint32_t abase = sbase;
    const uint32_t bbase = sbase + B_OFF;

    const int tid  = threadIdx.x;
    const int lane = tid & 31;
    const int wid  = tid >> 5;
    const int b = blockIdx.y;
    const int h = blockIdx.x;
    const int ci   = lane & 7;     // channel within chunk
    const int slot = lane >> 3;    // task slot (0..3)

    float c_[8][4];
    #pragma unroll
    for (int nt = 0; nt < 8; ++nt)
        #pragma unroll
        for (int i = 0; i < 4; ++i) c_[nt][i] = 0.f;

    // zero-init A (pad cols must be 0; data cols fully rewritten each chunk)
    for (int i = tid; i < A_BYTES/4; i += 256) ((uint32_t*)sm)[i] = 0;

    const float* xtb = g_xt + (size_t)b * HW_ * C_;
    const size_t recbase = (size_t)(b*HW_ + h*W_) * 9;

    // ldmatrix lane addresses
    const uint32_t a_lane = abase + (uint32_t)(wid*16 + (lane & 15))*(AST2_*2)
                                  + (uint32_t)(lane >> 4)*16;
    const uint32_t b_row  = (uint32_t)((lane & 7) + ((lane >> 3) & 1)*8);
    const uint32_t b_lane = bbase + b_row*(BST_*2) + (uint32_t)(lane >> 4)*16;

    for (int cc = 0; cc < NCH_; ++cc) {
        __syncthreads();   // prior mma reads done before overwriting A/B
        // ---- B chunk: gmem [240][64] -> smem [240][72] ----
        {
            const char* src = (const char*)(g_wb + (size_t)cc*BROWS_*O_);
            for (int i = tid; i < BROWS_*8; i += 256) {
                int row = i >> 3, seg = i & 7;
                *(float4*)(sm + B_OFF + row*(BST_*2) + seg*16) =
                    *(const float4*)(src + (row*O_ + seg*8)*2);
            }
        }
        // ---- sampling: 1152 tasks x 8 channels ----
        {
            const float* xc = xtb + cc*CPC_ + ci;
            #pragma unroll 2
            for (int it = 0; it < 36; ++it) {
                int t = it*32 + wid*4 + slot;
                int p = t & 127;
                int k = t >> 7;
                float4 wv = g_recw[recbase + (size_t)p*9 + k];
                int4   rv = g_recr[recbase + (size_t)p*9 + k];
                float s = wv.x*__ldg(xc + rv.x) + wv.y*__ldg(xc + rv.y)
                        + wv.z*__ldg(xc + rv.z) + wv.w*__ldg(xc + rv.w);
                __nv_bfloat16 vh = __float2bfloat16(s);
                __nv_bfloat16 vl = __float2bfloat16(s - __bfloat162float(vh));
                int jl = ci*9 + k;
                __nv_bfloat16* ar = Ap + p*AST2_;
                ar[jl]       = vh;
                ar[KB_ + jl] = vl;
            }
        }
        __syncthreads();
        // ---- mma: 15 k-steps ----
        #pragma unroll
        for (int s = 0; s < 15; ++s) {
            const uint32_t coloff = (s < 5) ? (uint32_t)s*32
                                  : (s < 10) ? (uint32_t)(s-5)*32
                                  : 160u + (uint32_t)(s-10)*32;
            uint32_t a0, a1, a2, a3;
            ldsm_x4(a0, a1, a2, a3, a_lane + coloff);
            uint32_t brow = b_lane + (uint32_t)s*16*(BST_*2);
            #pragma unroll
            for (int np = 0; np < 4; ++np) {
                uint32_t b0, b1, b2, b3;
                ldsm_x4_t(b0, b1, b2, b3, brow + (uint32_t)np*32);
                mma16816(c_[2*np    ], a0, a1, a2, a3, b0, b1);
                mma16816(c_[2*np + 1], a0, a1, a2, a3, b2, b3);
            }
        }
    }

    // ---- epilogue: stage to [o][px] fp32 in smem, then coalesced out ----
    __syncthreads();
    {
        int pxl = wid*16 + (lane >> 2);
        int oc  = (lane & 3)*2;
        #pragma unroll
        for (int nt = 0; nt < 8; ++nt) {
            int o = nt*8 + oc;
            stg[(o    )*128 + pxl    ] = c_[nt][0];
            stg[(o + 1)*128 + pxl    ] = c_[nt][1];
            stg[(o    )*128 + pxl + 8] = c_[nt][2];
            stg[(o + 1)*128 + pxl + 8] = c_[nt][3];
        }
    }
    __syncthreads();
    #pragma unroll
    for (int o8 = 0; o8 < 8; ++o8) {
        int o = wid*8 + o8;
        float bv = bias[o];
        size_t ob = ((size_t)(b*O_ + o))*HW_ + (size_t)h*W_;
        #pragma unroll
        for (int q = 0; q < 4; ++q)
            out[ob + q*32 + lane] = stg[o*128 + q*32 + lane] + bv;
    }
}

// ---------------- launch ----------------
extern "C" void kernel_launch(void* const* d_in, const int* in_sizes, int n_in,
                              void* d_out, int out_size) {
    (void)in_sizes; (void)n_in; (void)out_size;
    const float* x     = (const float*)d_in[0];
    const float* w_off = (const float*)d_in[1];
    const float* b_off = (const float*)d_in[2];
    const float* w_mod = (const float*)d_in[3];
    const float* b_mod = (const float*)d_in[4];
    const float* w     = (const float*)d_in[5];
    const float* bias  = (const float*)d_in[6];
    float* out = (float*)d_out;

    cudaFuncSetAttribute(sample_mma_kernel,
                         cudaFuncAttributeMaxDynamicSharedMemorySize, SMEM_C);

    transpose_kernel<<<dim3(HW_/32, C_/32, B_), dim3(32, 8)>>>(x);
    wb_kernel<<<(NCH_*BROWS_*O_ + 255)/256, 256>>>(w);
    conv_kernel<<<dim3(H_/2, B_), 128>>>(x, w_off, b_off, w_mod, b_mod);
    sample_mma_kernel<<<dim3(H_, B_), 256, SMEM_C>>>(bias, out);
}